// round 8
// baseline (speedup 1.0000x reference)
#include <cuda_runtime.h>
#include <cuda_fp16.h>
#include <cstdint>
#include <math.h>

#define Bsz 2
#define Lseq 4096
#define DM 768
#define DS 16
#define EE 1536
#define NROWS (Bsz*Lseq)      // 8192
#define KCAT 1568             // 1536 (xact) + 16 (us) + 16 (zero pad)
#define KC_CAT 98             // KCAT/16
#define LN_EPS 1e-5f

#define STAGES 4
#define STAGE_BYTES 16384

// ======================= small PTX helpers ==================================
__device__ __forceinline__ uint32_t smem_u32(const void* p) {
    uint32_t a;
    asm("{ .reg .u64 t; cvta.to.shared.u64 t, %1; cvt.u32.u64 %0, t; }"
        : "=r"(a) : "l"(p));
    return a;
}
__device__ __forceinline__ void cp_async16(uint32_t dst, const void* src) {
    asm volatile("cp.async.cg.shared.global [%0], [%1], 16;"
                 :: "r"(dst), "l"(src) : "memory");
}
__device__ __forceinline__ void cp_commit() {
    asm volatile("cp.async.commit_group;" ::: "memory");
}
template<int N> __device__ __forceinline__ void cp_wait() {
    asm volatile("cp.async.wait_group %0;" :: "n"(N) : "memory");
}
__device__ __forceinline__ void mma_f16(float* c, const uint32_t* a, const uint32_t* b) {
    asm volatile("mma.sync.aligned.m16n8k16.row.col.f32.f16.f16.f32 "
        "{%0,%1,%2,%3}, {%4,%5,%6,%7}, {%8,%9}, {%0,%1,%2,%3};"
        : "+f"(c[0]), "+f"(c[1]), "+f"(c[2]), "+f"(c[3])
        : "r"(a[0]), "r"(a[1]), "r"(a[2]), "r"(a[3]), "r"(b[0]), "r"(b[1]));
}

// ---- fp16 fragment-native layouts (half-element index) ----------------------
__device__ __forceinline__ size_t afh_idx(int r, int k, int KC16) {
    size_t blk = (size_t)((r >> 4) * KC16 + (k >> 4));
    int b32 = (r & 7) * 16 + ((k >> 1) & 3) * 4 + ((r >> 3) & 1) + 2 * ((k >> 3) & 1);
    return blk * 256 + b32 * 2 + (k & 1);
}
__device__ __forceinline__ size_t bfh_idx(int n, int k, int KC16) {
    size_t blk = (size_t)((n >> 3) * KC16 + (k >> 4));
    int b32 = (n & 7) * 8 + ((k >> 1) & 3) * 2 + ((k >> 3) & 1);
    return blk * 128 + b32 * 2 + (k & 1);
}
__device__ __forceinline__ void bfh_inv(int idx, int KC16, int& n, int& k) {
    int blk = idx >> 7;
    int b32 = (idx & 127) >> 1, h = idx & 1;
    n = (blk / KC16) * 8 + (b32 >> 3);
    k = ((blk % KC16) << 4) | ((b32 & 1) << 3) | (((b32 >> 1) & 3) << 1) | h;
}
__device__ __forceinline__ void afh_inv(int idx, int KC16, int& r, int& k) {
    int blk = idx >> 8;
    int b32 = (idx & 255) >> 1, h = idx & 1;
    r = (blk / KC16) * 16 + ((b32 & 1) << 3) + (b32 >> 4);
    k = ((blk % KC16) << 4) | (((b32 >> 1) & 1) << 3) | (((b32 >> 2) & 3) << 1) | h;
}

// ======================= scratch ============================================
__device__ __align__(256) __half g_xn    [NROWS * DM];     // A_f (K=768)
__device__ __align__(256) __half g_xin   [NROWS * EE];     // fp16 row-major
__device__ __align__(256) __half g_cat   [NROWS * KCAT];   // A_f (K=1568): xact|us|0
__device__ __align__(256) float  g_xd    [NROWS * 32];     // ds|dt_raw
__device__ float g_dt [NROWS * DS];
__device__ float g_bt [NROWS * DS];
__device__ float g_v  [NROWS * DS];
__device__ float g_bias32[32];
__device__ float g_cbias [DM];
__device__ __align__(256) __half g_winF  [EE * DM];        // B_f: N=1536, K=768
__device__ __align__(256) __half g_wpsF  [128 * EE];       // B_f: N=128(pad), K=1536
__device__ __align__(256) __half g_xplF  [EE * DM];        // A_f: W_xp_low (M=1536,K=768)
__device__ __align__(256) __half g_wolF  [DM * DM];        // B_f: W_out_low (N=768,K=768)
__device__ __align__(256) __half g_comboF[(DM/8) * KC_CAT * 128]; // B_f: N=768, K=1568

// ======================= fp16 mma.sync GEMM =================================
// MODE 0: float row-major out (+bias)   MODE 1: half row-major out (+bias)
// MODE 2: half out in bfh layout (k=row, n=col, KC16=98), += addW for row>=768
template<int MODE>
__global__ __launch_bounds__(256, 2) void gemm_f16_kernel(
    const __half* __restrict__ Af, int kc16s,
    const __half* __restrict__ Bf,
    const float* __restrict__ bias, void* __restrict__ Cv,
    int ldc, int Ndim, int K, const float* __restrict__ addW)
{
    extern __shared__ __align__(16) char sm[];
    const int tid = threadIdx.x;
    const int wid = tid >> 5, lane = tid & 31;
    const int wm = wid >> 1, wn = wid & 1;
    const int g = lane >> 2, tg = lane & 3;
    const int KC16 = K >> 4, NC = K >> 5;
    const int mp0 = blockIdx.y * 8;
    const int ng0 = blockIdx.x * 16;
    const int m0 = blockIdx.y * 128, n0 = blockIdx.x * 128;
    const uint32_t smb = smem_u32(sm);

    const __half* a_src0 = Af + ((size_t)(mp0 + (tid >> 6)) * kc16s) * 256 + (tid & 63) * 8;
    const __half* a_src1 = Af + ((size_t)(mp0 + (tid >> 6) + 4) * kc16s) * 256 + (tid & 63) * 8;
    const __half* b_src0 = Bf + ((size_t)(ng0 + (tid >> 5)) * KC16) * 128 + (tid & 31) * 8;
    const __half* b_src1 = Bf + ((size_t)(ng0 + (tid >> 5) + 8) * KC16) * 128 + (tid & 31) * 8;
    const uint32_t a_dst0 = smb + (uint32_t)tid * 16u;
    const uint32_t a_dst1 = smb + (uint32_t)(tid + 256) * 16u;
    const uint32_t b_dst0 = smb + 8192u + (uint32_t)tid * 16u;
    const uint32_t b_dst1 = smb + 8192u + (uint32_t)(tid + 256) * 16u;

    auto load_chunk = [&](int c) {
        const uint32_t st = (uint32_t)(c & 3) * STAGE_BYTES;
        cp_async16(a_dst0 + st, a_src0 + (size_t)c * 512);
        cp_async16(a_dst1 + st, a_src1 + (size_t)c * 512);
        cp_async16(b_dst0 + st, b_src0 + (size_t)c * 256);
        cp_async16(b_dst1 + st, b_src1 + (size_t)c * 256);
        cp_commit();
    };

    float acc[2][8][4];
    #pragma unroll
    for (int mi = 0; mi < 2; mi++)
        #pragma unroll
        for (int ni = 0; ni < 8; ni++)
            #pragma unroll
            for (int q = 0; q < 4; q++) acc[mi][ni][q] = 0.0f;

    load_chunk(0); load_chunk(1); load_chunk(2);

    const char* stA_base = sm + wm * 2048 + g * 64 + tg * 16;
    const char* stB_base = sm + 8192 + wn * 4096 + g * 32 + tg * 8;

    for (int c = 0; c < NC; c++) {
        cp_wait<2>();
        __syncthreads();
        if (c + 3 < NC) load_chunk(c + 3); else cp_commit();

        const char* stA = stA_base + (c & 3) * STAGE_BYTES;
        const char* stB = stB_base + (c & 3) * STAGE_BYTES;

        #pragma unroll
        for (int kb = 0; kb < 2; kb++) {
            uint4 a0 = *(const uint4*)(stA + kb * 512);
            uint4 a1 = *(const uint4*)(stA + 1024 + kb * 512);
            uint2 bq[8];
            #pragma unroll
            for (int ni = 0; ni < 8; ni++)
                bq[ni] = *(const uint2*)(stB + ni * 512 + kb * 256);
            #pragma unroll
            for (int ni = 0; ni < 8; ni++) {
                mma_f16(acc[0][ni], (const uint32_t*)&a0, (const uint32_t*)&bq[ni]);
                mma_f16(acc[1][ni], (const uint32_t*)&a1, (const uint32_t*)&bq[ni]);
            }
        }
    }

    if (MODE == 2) {
        __half* Cc = (__half*)Cv;
        #pragma unroll
        for (int mi = 0; mi < 2; mi++)
            #pragma unroll
            for (int ni = 0; ni < 8; ni++)
                #pragma unroll
                for (int q = 0; q < 4; q++) {
                    int row = m0 + wm * 32 + mi * 16 + g + ((q >> 1) << 3);
                    int col = n0 + wn * 64 + ni * 8 + tg * 2 + (q & 1);
                    float v = acc[mi][ni][q];
                    if (row >= DM) v += addW[(size_t)row * DM + col];
                    Cc[bfh_idx(col, row, KC_CAT)] = __float2half_rn(v);
                }
    } else {
        #pragma unroll
        for (int mi = 0; mi < 2; mi++) {
            const int row = m0 + wm * 32 + mi * 16 + g;
            #pragma unroll
            for (int ni = 0; ni < 8; ni++) {
                const int col = n0 + wn * 64 + ni * 8 + tg * 2;
                if (col < Ndim) {
                    float bx = bias[col], by = bias[col + 1];
                    float v00 = acc[mi][ni][0] + bx, v01 = acc[mi][ni][1] + by;
                    float v10 = acc[mi][ni][2] + bx, v11 = acc[mi][ni][3] + by;
                    if (MODE == 1) {
                        __half* c0 = (__half*)Cv + (size_t)row * ldc;
                        __half* c1 = (__half*)Cv + (size_t)(row + 8) * ldc;
                        *(__half2*)(c0 + col) = __floats2half2_rn(v00, v01);
                        *(__half2*)(c1 + col) = __floats2half2_rn(v10, v11);
                    } else {
                        float* c0 = (float*)Cv + (size_t)row * ldc;
                        float* c1 = (float*)Cv + (size_t)(row + 8) * ldc;
                        *(float2*)(c0 + col) = make_float2(v00, v01);
                        *(float2*)(c1 + col) = make_float2(v10, v11);
                    }
                }
            }
        }
    }
}

// ======================= LayerNorm -> A_f fp16 (K=768) ======================
__global__ __launch_bounds__(256) void ln_kernel(const float* __restrict__ x,
                                                 const float* __restrict__ g,
                                                 const float* __restrict__ b) {
    int row = blockIdx.x, tid = threadIdx.x;
    const float* xr = x + (size_t)row * DM;
    float v0 = xr[tid], v1 = xr[tid + 256], v2 = xr[tid + 512];
    __shared__ float red[256];
    red[tid] = v0 + v1 + v2; __syncthreads();
    for (int off = 128; off > 0; off >>= 1) {
        if (tid < off) red[tid] += red[tid + off];
        __syncthreads();
    }
    float mu = red[0] * (1.0f / DM); __syncthreads();
    float d0 = v0 - mu, d1 = v1 - mu, d2 = v2 - mu;
    red[tid] = d0*d0 + d1*d1 + d2*d2; __syncthreads();
    for (int off = 128; off > 0; off >>= 1) {
        if (tid < off) red[tid] += red[tid + off];
        __syncthreads();
    }
    float rstd = rsqrtf(red[0] * (1.0f / DM) + LN_EPS);
    g_xn[afh_idx(row, tid,       48)] = __float2half_rn(d0 * rstd * g[tid]       + b[tid]);
    g_xn[afh_idx(row, tid + 256, 48)] = __float2half_rn(d1 * rstd * g[tid + 256] + b[tid + 256]);
    g_xn[afh_idx(row, tid + 512, 48)] = __float2half_rn(d2 * rstd * g[tid + 512] + b[tid + 512]);
}

// ======================= format kernels =====================================
__global__ void bfmt_kernel(const float* __restrict__ W, __half* __restrict__ Bf,
                            int N, int KC16) {  // W row-major [K][N]
    int idx = blockIdx.x * blockDim.x + threadIdx.x;
    int n, k; bfh_inv(idx, KC16, n, k);
    Bf[idx] = __float2half_rn(W[(size_t)k * N + n]);
}

// W_xp_low -> A_f (M=1536 rows of W_xp, K=768 cols); W_xp row stride 784
__global__ void afmt_xpl_kernel(const float* __restrict__ W_xp) {
    int idx = blockIdx.x * blockDim.x + threadIdx.x;  // < 1536*768
    int r, k; afh_inv(idx, 48, r, k);
    g_xplF[idx] = __float2half_rn(W_xp[(size_t)r * (DM + DS) + k]);
}

// [W_xp[:,768:784] | W_dt | 0] -> B_f N=128(pad), K=1536 ; plus bias32
__global__ void bfmt_small_kernel(const float* __restrict__ W_xp,
                                  const float* __restrict__ W_dt,
                                  const float* __restrict__ b_xp,
                                  const float* __restrict__ b_dt) {
    int idx = blockIdx.x * blockDim.x + threadIdx.x;
    if (idx < 128 * EE) {
        int n, k; bfh_inv(idx, 96, n, k);
        float v = (n < DS)     ? W_xp[(size_t)k * (DM + DS) + DM + n]
                : (n < 2 * DS) ? W_dt[(size_t)k * DS + (n - DS)]
                : 0.0f;
        g_wpsF[idx] = __float2half_rn(v);
    }
    if (idx < 32)
        g_bias32[idx] = (idx < DS) ? b_xp[DM + idx] : b_dt[idx - DS];
}

// W_us2 = W_us @ W_out_low -> comboF k-rows [1536,1568) (s>=16 rows are zero)
__global__ void wus2_kernel(const float* __restrict__ W_us,
                            const float* __restrict__ W_out) {
    int idx = blockIdx.x * blockDim.x + threadIdx.x;  // < 768*32
    int n = idx >> 5, s = idx & 31;
    float acc = 0.0f;
    if (s < DS) {
        for (int j = 0; j < DM; j++)
            acc += W_us[(size_t)s * DM + j] * W_out[(size_t)j * DM + n];
    }
    g_comboF[bfh_idx(n, EE + s, KC_CAT)] = __float2half_rn(acc);
}

// cbias = (b_xp_low + b_us) @ W_out_low + b_out
__global__ void cbias_kernel(const float* __restrict__ b_xp,
                             const float* __restrict__ b_us,
                             const float* __restrict__ W_out,
                             const float* __restrict__ b_out) {
    int n = blockIdx.x * blockDim.x + threadIdx.x;
    if (n >= DM) return;
    float acc = b_out[n];
    for (int j = 0; j < DM; j++)
        acc += (b_xp[j] + b_us[j]) * W_out[(size_t)j * DM + n];
    g_cbias[n] = acc;
}

// ======================= depthwise conv (k=4) + SiLU -> g_cat A_f ===========
__global__ void conv_silu_kernel(const float* __restrict__ b_conv,
                                 const float* __restrict__ W_conv) {
    int idx = blockIdx.x * blockDim.x + threadIdx.x;
    if (idx >= (NROWS / 4) * EE) return;
    int e = idx % EE;
    int r0 = (idx / EE) * 4;
    int l0 = r0 % Lseq;
    const float4 w = *(const float4*)(W_conv + e * 4);
    float bc = b_conv[e];
    float x0 = (l0 >= 3) ? __half2float(g_xin[(size_t)(r0 - 3) * EE + e]) : 0.f;
    float x1 = (l0 >= 2) ? __half2float(g_xin[(size_t)(r0 - 2) * EE + e]) : 0.f;
    float x2 = (l0 >= 1) ? __half2float(g_xin[(size_t)(r0 - 1) * EE + e]) : 0.f;
    float x3 = __half2float(g_xin[(size_t)(r0 + 0) * EE + e]);
    float x4 = __half2float(g_xin[(size_t)(r0 + 1) * EE + e]);
    float x5 = __half2float(g_xin[(size_t)(r0 + 2) * EE + e]);
    float x6 = __half2float(g_xin[(size_t)(r0 + 3) * EE + e]);
    float s0 = bc + x0 * w.x + x1 * w.y + x2 * w.z + x3 * w.w;
    float s1 = bc + x1 * w.x + x2 * w.y + x3 * w.z + x4 * w.w;
    float s2 = bc + x2 * w.x + x3 * w.y + x4 * w.z + x5 * w.w;
    float s3 = bc + x3 * w.x + x4 * w.y + x5 * w.z + x6 * w.w;
    g_cat[afh_idx(r0 + 0, e, KC_CAT)] = __float2half_rn(s0 / (1.0f + expf(-s0)));
    g_cat[afh_idx(r0 + 1, e, KC_CAT)] = __float2half_rn(s1 / (1.0f + expf(-s1)));
    g_cat[afh_idx(r0 + 2, e, KC_CAT)] = __float2half_rn(s2 / (1.0f + expf(-s2)));
    g_cat[afh_idx(r0 + 3, e, KC_CAT)] = __float2half_rn(s3 / (1.0f + expf(-s3)));
}

// ======================= fused prescan + parallel scan ======================
__global__ __launch_bounds__(256) void scan_kernel() {
    int chan = blockIdx.x;
    int bb = chan / DS, s = chan % DS;
    int t = threadIdx.x;
    __shared__ float sA[256], sB[256];
    float A = 1.0f, Bl = 0.0f;
    int base = bb * Lseq;
    #pragma unroll 4
    for (int i = 0; i < 16; i++) {
        size_t rofs = (size_t)(base + t * 16 + i);
        float ds    = g_xd[rofs * 32 + s];
        float dtraw = g_xd[rofs * 32 + 16 + s];
        float dt = fmaxf(dtraw, 0.0f) + log1pf(expf(-fabsf(dtraw)));
        float bt = ds * expf(-0.5f * dt);
        g_dt[rofs * DS + s] = dt;
        g_bt[rofs * DS + s] = bt;
        float a = expf(-dt);
        Bl = a * Bl + bt;
        A = a * A;
    }
    sA[t] = A; sB[t] = Bl;
    __syncthreads();
    for (int offp = 1; offp < 256; offp <<= 1) {
        float pA = 0.f, pB = 0.f;
        bool has = (t >= offp);
        if (has) { pA = sA[t - offp]; pB = sB[t - offp]; }
        __syncthreads();
        if (has) { sB[t] = sA[t] * pB + sB[t]; sA[t] = sA[t] * pA; }
        __syncthreads();
    }
    float v = (t == 0) ? 0.0f : sB[t - 1];
    for (int i = 0; i < 16; i++) {
        size_t off = (size_t)(base + t * 16 + i) * DS + s;
        float a = expf(-g_dt[off]);
        v = a * v + g_bt[off];
        g_v[off] = v;
    }
}

// ======================= us -> g_cat k-blocks 96/97 =========================
__global__ void us_kernel() {
    int idx = blockIdx.x * blockDim.x + threadIdx.x;
    if (idx >= NROWS * DS) return;
    int row = idx >> 4, s = idx & 15;
    int l = row % Lseq;
    float kf = (float)(Lseq - 1 - l);
    size_t off = (size_t)row * DS + s;
    float dt = g_dt[off], v = g_v[off], bt = g_bt[off];
    float denom = expm1f(-dt);
    if (denom > -1e-30f) denom = -1e-30f;
    float us = expf(-kf * dt) * v + bt * expm1f(-kf * dt) / denom;
    g_cat[afh_idx(row, EE + s,      KC_CAT)] = __float2half_rn(us);
    g_cat[afh_idx(row, EE + DS + s, KC_CAT)] = __half(0.0f);
}

// ======================= launch =============================================
extern "C" void kernel_launch(void* const* d_in, const int* in_sizes, int n_in,
                              void* d_out, int out_size) {
    const float* x      = (const float*)d_in[0];
    const float* ln_g   = (const float*)d_in[1];
    const float* ln_b   = (const float*)d_in[2];
    const float* W_in   = (const float*)d_in[3];
    const float* b_in   = (const float*)d_in[4];
    const float* W_conv = (const float*)d_in[5];
    const float* b_conv = (const float*)d_in[6];
    const float* W_xp   = (const float*)d_in[7];
    const float* b_xp   = (const float*)d_in[8];
    const float* W_dt   = (const float*)d_in[9];
    const float* b_dt   = (const float*)d_in[10];
    const float* W_us   = (const float*)d_in[11];
    const float* b_us   = (const float*)d_in[12];
    const float* W_out  = (const float*)d_in[13];
    const float* b_out  = (const float*)d_in[14];
    float* out = (float*)d_out;

    __half *xn, *xin, *cat, *winF, *wpsF, *xplF, *wolF, *comboF;
    float *xd, *bias32, *cbias;
    cudaGetSymbolAddress((void**)&xn,     g_xn);
    cudaGetSymbolAddress((void**)&xin,    g_xin);
    cudaGetSymbolAddress((void**)&cat,    g_cat);
    cudaGetSymbolAddress((void**)&xd,     g_xd);
    cudaGetSymbolAddress((void**)&bias32, g_bias32);
    cudaGetSymbolAddress((void**)&cbias,  g_cbias);
    cudaGetSymbolAddress((void**)&winF,   g_winF);
    cudaGetSymbolAddress((void**)&wpsF,   g_wpsF);
    cudaGetSymbolAddress((void**)&xplF,   g_xplF);
    cudaGetSymbolAddress((void**)&wolF,   g_wolF);
    cudaGetSymbolAddress((void**)&comboF, g_comboF);

    const int GEMM_SMEM = STAGES * STAGE_BYTES;  // 65536
    cudaFuncSetAttribute(gemm_f16_kernel<0>, cudaFuncAttributeMaxDynamicSharedMemorySize, GEMM_SMEM);
    cudaFuncSetAttribute(gemm_f16_kernel<1>, cudaFuncAttributeMaxDynamicSharedMemorySize, GEMM_SMEM);
    cudaFuncSetAttribute(gemm_f16_kernel<2>, cudaFuncAttributeMaxDynamicSharedMemorySize, GEMM_SMEM);

    // ---- weight prep ----
    bfmt_kernel<<<(EE * DM) / 256, 256>>>(W_in, winF, EE, 48);     // N=1536,K=768
    bfmt_kernel<<<(DM * DM) / 256, 256>>>(W_out, wolF, DM, 48);    // W_out_low: N=768,K=768
    afmt_xpl_kernel<<<(EE * DM) / 256, 256>>>(W_xp);
    bfmt_small_kernel<<<(128 * EE + 255) / 256, 256>>>(W_xp, W_dt, b_xp, b_dt);
    wus2_kernel<<<(DM * 32 + 255) / 256, 256>>>(W_us, W_out);
    cbias_kernel<<<3, 256>>>(b_xp, b_us, W_out, b_out);
    // W_combo rows [0,1536): xplF(1536x768) @ wolF^T + W_out_hi -> comboF (MODE 2)
    gemm_f16_kernel<2><<<dim3(DM/128, EE/128), 256, GEMM_SMEM>>>(
        xplF, 48, wolF, nullptr, comboF, 0, DM, DM, W_out);

    // ---- activation pipeline ----
    ln_kernel<<<NROWS, 256>>>(x, ln_g, ln_b);
    // in-proj: (8192x768)@(768x1536) -> xin fp16 row-major
    gemm_f16_kernel<1><<<dim3(EE/128, NROWS/128), 256, GEMM_SMEM>>>(
        xn, 48, winF, b_in, xin, EE, EE, DM, nullptr);
    conv_silu_kernel<<<((NROWS/4) * EE + 255) / 256, 256>>>(b_conv, W_conv);
    // small proj: (8192x1536)@(1536x32) -> xd (ds|dt_raw)
    gemm_f16_kernel<0><<<dim3(1, NROWS/128), 256, GEMM_SMEM>>>(
        cat, KC_CAT, wpsF, bias32, xd, 32, 32, EE, nullptr);
    scan_kernel<<<Bsz * DS, 256>>>();
    us_kernel<<<(NROWS * DS + 255) / 256, 256>>>();
    // final: (8192x1568)@(1568x768) + cbias -> out
    gemm_f16_kernel<0><<<dim3(DM/128, NROWS/128), 256, GEMM_SMEM>>>(
        cat, KC_CAT, comboF, cbias, out, DM, DM, KCAT, nullptr);
}

// round 9
// speedup vs baseline: 1.1930x; 1.1930x over previous
#include <cuda_runtime.h>
#include <cuda_fp16.h>
#include <cstdint>
#include <math.h>

#define Bsz 2
#define Lseq 4096
#define DM 768
#define DS 16
#define EE 1536
#define NROWS (Bsz*Lseq)      // 8192
#define KCAT 1568             // 1536 (xact) + 16 (us) + 16 (zero pad)
#define KC_CAT 98             // KCAT/16
#define LN_EPS 1e-5f

#define STAGES 4
#define STAGE_BYTES 16384

// prep kernel block-region boundaries
#define NB_WIN  4608          // EE*DM/256
#define NB_WOL  (NB_WIN + 2304)
#define NB_XPL  (NB_WOL + 4608)
#define NB_WPS  (NB_XPL + 768)
#define NB_WUS2 (NB_WPS + 24)
#define NB_CB   (NB_WUS2 + 3)

// ======================= small PTX helpers ==================================
__device__ __forceinline__ uint32_t smem_u32(const void* p) {
    uint32_t a;
    asm("{ .reg .u64 t; cvta.to.shared.u64 t, %1; cvt.u32.u64 %0, t; }"
        : "=r"(a) : "l"(p));
    return a;
}
__device__ __forceinline__ void cp_async16(uint32_t dst, const void* src) {
    asm volatile("cp.async.cg.shared.global [%0], [%1], 16;"
                 :: "r"(dst), "l"(src) : "memory");
}
__device__ __forceinline__ void cp_commit() {
    asm volatile("cp.async.commit_group;" ::: "memory");
}
template<int N> __device__ __forceinline__ void cp_wait() {
    asm volatile("cp.async.wait_group %0;" :: "n"(N) : "memory");
}
__device__ __forceinline__ void mma_f16(float* c, const uint32_t* a, const uint32_t* b) {
    asm volatile("mma.sync.aligned.m16n8k16.row.col.f32.f16.f16.f32 "
        "{%0,%1,%2,%3}, {%4,%5,%6,%7}, {%8,%9}, {%0,%1,%2,%3};"
        : "+f"(c[0]), "+f"(c[1]), "+f"(c[2]), "+f"(c[3])
        : "r"(a[0]), "r"(a[1]), "r"(a[2]), "r"(a[3]), "r"(b[0]), "r"(b[1]));
}

// ---- fp16 fragment-native layouts (half-element index) ----------------------
__device__ __forceinline__ size_t afh_idx(int r, int k, int KC16) {
    size_t blk = (size_t)((r >> 4) * KC16 + (k >> 4));
    int b32 = (r & 7) * 16 + ((k >> 1) & 3) * 4 + ((r >> 3) & 1) + 2 * ((k >> 3) & 1);
    return blk * 256 + b32 * 2 + (k & 1);
}
__device__ __forceinline__ size_t bfh_idx(int n, int k, int KC16) {
    size_t blk = (size_t)((n >> 3) * KC16 + (k >> 4));
    int b32 = (n & 7) * 8 + ((k >> 1) & 3) * 2 + ((k >> 3) & 1);
    return blk * 128 + b32 * 2 + (k & 1);
}
__device__ __forceinline__ void bfh_inv(int idx, int KC16, int& n, int& k) {
    int blk = idx >> 7;
    int b32 = (idx & 127) >> 1, h = idx & 1;
    n = (blk / KC16) * 8 + (b32 >> 3);
    k = ((blk % KC16) << 4) | ((b32 & 1) << 3) | (((b32 >> 1) & 3) << 1) | h;
}
__device__ __forceinline__ void afh_inv(int idx, int KC16, int& r, int& k) {
    int blk = idx >> 8;
    int b32 = (idx & 255) >> 1, h = idx & 1;
    r = (blk / KC16) * 16 + ((b32 & 1) << 3) + (b32 >> 4);
    k = ((blk % KC16) << 4) | (((b32 >> 1) & 1) << 3) | (((b32 >> 2) & 3) << 1) | h;
}

// ======================= scratch ============================================
__device__ __align__(256) __half g_xn    [NROWS * DM];     // A_f (K=768)
__device__ __align__(256) __half g_xin   [NROWS * EE];     // fp16 row-major
__device__ __align__(256) __half g_cat   [NROWS * KCAT];   // A_f (K=1568): xact|us|0
__device__ __align__(256) float  g_xd    [NROWS * 32];     // ds|dt_raw
__device__ float g_dt [NROWS * DS];
__device__ float g_bt [NROWS * DS];
__device__ float g_bias32[32];
__device__ float g_cbias [DM];
__device__ __align__(256) __half g_winF  [EE * DM];        // B_f: N=1536, K=768
__device__ __align__(256) __half g_wpsF  [128 * EE];       // B_f: N=128(pad), K=1536
__device__ __align__(256) __half g_xplF  [EE * DM];        // A_f: W_xp_low (M=1536,K=768)
__device__ __align__(256) __half g_wolF  [DM * DM];        // B_f: W_out_low (N=768,K=768)
__device__ __align__(256) __half g_comboF[(DM/8) * KC_CAT * 128]; // B_f: N=768, K=1568

// ======================= fp16 mma.sync GEMM =================================
// MODE 0: float row-major out (+bias)   MODE 1: half row-major out (+bias)
// MODE 2: half out in bfh layout (k=row, n=col, KC16=98), += addW for row>=768
template<int MODE>
__global__ __launch_bounds__(256, 2) void gemm_f16_kernel(
    const __half* __restrict__ Af, int kc16s,
    const __half* __restrict__ Bf,
    const float* __restrict__ bias, void* __restrict__ Cv,
    int ldc, int Ndim, int K, const float* __restrict__ addW)
{
    extern __shared__ __align__(16) char sm[];
    const int tid = threadIdx.x;
    const int wid = tid >> 5, lane = tid & 31;
    const int wm = wid >> 1, wn = wid & 1;
    const int g = lane >> 2, tg = lane & 3;
    const int KC16 = K >> 4, NC = K >> 5;
    const int mp0 = blockIdx.y * 8;
    const int ng0 = blockIdx.x * 16;
    const int m0 = blockIdx.y * 128, n0 = blockIdx.x * 128;
    const uint32_t smb = smem_u32(sm);

    const __half* a_src0 = Af + ((size_t)(mp0 + (tid >> 6)) * kc16s) * 256 + (tid & 63) * 8;
    const __half* a_src1 = Af + ((size_t)(mp0 + (tid >> 6) + 4) * kc16s) * 256 + (tid & 63) * 8;
    const __half* b_src0 = Bf + ((size_t)(ng0 + (tid >> 5)) * KC16) * 128 + (tid & 31) * 8;
    const __half* b_src1 = Bf + ((size_t)(ng0 + (tid >> 5) + 8) * KC16) * 128 + (tid & 31) * 8;
    const uint32_t a_dst0 = smb + (uint32_t)tid * 16u;
    const uint32_t a_dst1 = smb + (uint32_t)(tid + 256) * 16u;
    const uint32_t b_dst0 = smb + 8192u + (uint32_t)tid * 16u;
    const uint32_t b_dst1 = smb + 8192u + (uint32_t)(tid + 256) * 16u;

    auto load_chunk = [&](int c) {
        const uint32_t st = (uint32_t)(c & 3) * STAGE_BYTES;
        cp_async16(a_dst0 + st, a_src0 + (size_t)c * 512);
        cp_async16(a_dst1 + st, a_src1 + (size_t)c * 512);
        cp_async16(b_dst0 + st, b_src0 + (size_t)c * 256);
        cp_async16(b_dst1 + st, b_src1 + (size_t)c * 256);
        cp_commit();
    };

    float acc[2][8][4];
    #pragma unroll
    for (int mi = 0; mi < 2; mi++)
        #pragma unroll
        for (int ni = 0; ni < 8; ni++)
            #pragma unroll
            for (int q = 0; q < 4; q++) acc[mi][ni][q] = 0.0f;

    load_chunk(0); load_chunk(1); load_chunk(2);

    const char* stA_base = sm + wm * 2048 + g * 64 + tg * 16;
    const char* stB_base = sm + 8192 + wn * 4096 + g * 32 + tg * 8;

    for (int c = 0; c < NC; c++) {
        cp_wait<2>();
        __syncthreads();
        if (c + 3 < NC) load_chunk(c + 3); else cp_commit();

        const char* stA = stA_base + (c & 3) * STAGE_BYTES;
        const char* stB = stB_base + (c & 3) * STAGE_BYTES;

        #pragma unroll
        for (int kb = 0; kb < 2; kb++) {
            uint4 a0 = *(const uint4*)(stA + kb * 512);
            uint4 a1 = *(const uint4*)(stA + 1024 + kb * 512);
            uint2 bq[8];
            #pragma unroll
            for (int ni = 0; ni < 8; ni++)
                bq[ni] = *(const uint2*)(stB + ni * 512 + kb * 256);
            #pragma unroll
            for (int ni = 0; ni < 8; ni++) {
                mma_f16(acc[0][ni], (const uint32_t*)&a0, (const uint32_t*)&bq[ni]);
                mma_f16(acc[1][ni], (const uint32_t*)&a1, (const uint32_t*)&bq[ni]);
            }
        }
    }

    if (MODE == 2) {
        __half* Cc = (__half*)Cv;
        #pragma unroll
        for (int mi = 0; mi < 2; mi++)
            #pragma unroll
            for (int ni = 0; ni < 8; ni++)
                #pragma unroll
                for (int q = 0; q < 4; q++) {
                    int row = m0 + wm * 32 + mi * 16 + g + ((q >> 1) << 3);
                    int col = n0 + wn * 64 + ni * 8 + tg * 2 + (q & 1);
                    float v = acc[mi][ni][q];
                    if (row >= DM) v += addW[(size_t)row * DM + col];
                    Cc[bfh_idx(col, row, KC_CAT)] = __float2half_rn(v);
                }
    } else {
        #pragma unroll
        for (int mi = 0; mi < 2; mi++) {
            const int row = m0 + wm * 32 + mi * 16 + g;
            #pragma unroll
            for (int ni = 0; ni < 8; ni++) {
                const int col = n0 + wn * 64 + ni * 8 + tg * 2;
                if (col < Ndim) {
                    float bx = bias[col], by = bias[col + 1];
                    float v00 = acc[mi][ni][0] + bx, v01 = acc[mi][ni][1] + by;
                    float v10 = acc[mi][ni][2] + bx, v11 = acc[mi][ni][3] + by;
                    if (MODE == 1) {
                        __half* c0 = (__half*)Cv + (size_t)row * ldc;
                        __half* c1 = (__half*)Cv + (size_t)(row + 8) * ldc;
                        *(__half2*)(c0 + col) = __floats2half2_rn(v00, v01);
                        *(__half2*)(c1 + col) = __floats2half2_rn(v10, v11);
                    } else {
                        float* c0 = (float*)Cv + (size_t)row * ldc;
                        float* c1 = (float*)Cv + (size_t)(row + 8) * ldc;
                        *(float2*)(c0 + col) = make_float2(v00, v01);
                        *(float2*)(c1 + col) = make_float2(v10, v11);
                    }
                }
            }
        }
    }
}

// ======================= merged weight-prep kernel ==========================
__global__ void prep_kernel(const float* __restrict__ W_in,
                            const float* __restrict__ W_out,
                            const float* __restrict__ W_xp,
                            const float* __restrict__ W_dt,
                            const float* __restrict__ W_us,
                            const float* __restrict__ b_xp,
                            const float* __restrict__ b_dt,
                            const float* __restrict__ b_us,
                            const float* __restrict__ b_out) {
    __shared__ float red[8][16][32];
    const int blk = blockIdx.x;
    const int tid = threadIdx.x;

    if (blk < NB_WIN) {
        int idx = blk * 256 + tid;
        int n, k; bfh_inv(idx, 48, n, k);
        g_winF[idx] = __float2half_rn(W_in[(size_t)k * EE + n]);
    } else if (blk < NB_WOL) {
        int idx = (blk - NB_WIN) * 256 + tid;
        int n, k; bfh_inv(idx, 48, n, k);
        g_wolF[idx] = __float2half_rn(W_out[(size_t)k * DM + n]);
    } else if (blk < NB_XPL) {
        int idx = (blk - NB_WOL) * 256 + tid;
        int r, k; afh_inv(idx, 48, r, k);
        g_xplF[idx] = __float2half_rn(W_xp[(size_t)r * (DM + DS) + k]);
    } else if (blk < NB_WPS) {
        int idx = (blk - NB_XPL) * 256 + tid;
        int n, k; bfh_inv(idx, 96, n, k);
        float v = (n < DS)     ? W_xp[(size_t)k * (DM + DS) + DM + n]
                : (n < 2 * DS) ? W_dt[(size_t)k * DS + (n - DS)]
                : 0.0f;
        g_wpsF[idx] = __float2half_rn(v);
        if (blk == NB_XPL && tid < 32)
            g_bias32[tid] = (tid < DS) ? b_xp[DM + tid] : b_dt[tid - DS];
    } else if (blk < NB_WUS2) {
        // W_us2 = W_us(16x768) @ W_out_low(768x768): 24 blocks x 32 n each
        int bb = blk - NB_WPS;
        int n = bb * 32 + (tid & 31);
        int chunk = tid >> 5;          // 0..7 -> 96 j each
        float acc[16];
        #pragma unroll
        for (int s = 0; s < 16; s++) acc[s] = 0.0f;
        for (int j = chunk * 96; j < chunk * 96 + 96; j++) {
            float wo = W_out[(size_t)j * DM + n];
            #pragma unroll
            for (int s = 0; s < 16; s++)
                acc[s] = fmaf(W_us[(size_t)s * DM + j], wo, acc[s]);
        }
        #pragma unroll
        for (int s = 0; s < 16; s++) red[chunk][s][tid & 31] = acc[s];
        __syncthreads();
        for (int o = tid; o < 512; o += 256) {
            int s = o >> 5, ln = o & 31;
            float t = 0.0f;
            #pragma unroll
            for (int c = 0; c < 8; c++) t += red[c][s][ln];
            g_comboF[bfh_idx(bb * 32 + ln, EE + s,      KC_CAT)] = __float2half_rn(t);
            g_comboF[bfh_idx(bb * 32 + ln, EE + DS + s, KC_CAT)] = __half(0.0f);
        }
    } else {
        // cbias: 3 blocks x 256 n
        int n = (blk - NB_WUS2) * 256 + tid;
        float acc = b_out[n];
        for (int j = 0; j < DM; j++)
            acc = fmaf(b_xp[j] + b_us[j], W_out[(size_t)j * DM + n], acc);
        g_cbias[n] = acc;
    }
}

// ======================= LayerNorm -> A_f fp16 (K=768), 384 thr =============
__global__ __launch_bounds__(384) void ln_kernel(const float* __restrict__ x,
                                                 const float* __restrict__ g,
                                                 const float* __restrict__ b) {
    int row = blockIdx.x, tid = threadIdx.x;
    const float2* xr = (const float2*)(x + (size_t)row * DM);
    float2 v = xr[tid];
    __shared__ float red[512];
    if (tid < 128) red[384 + tid] = 0.0f;
    red[tid] = v.x + v.y;
    __syncthreads();
    for (int off = 256; off > 0; off >>= 1) {
        if (tid < off) red[tid] += red[tid + off];
        __syncthreads();
    }
    float mu = red[0] * (1.0f / DM);
    __syncthreads();
    float dx = v.x - mu, dy = v.y - mu;
    red[tid] = dx * dx + dy * dy;
    __syncthreads();
    for (int off = 256; off > 0; off >>= 1) {
        if (tid < off) red[tid] += red[tid + off];
        __syncthreads();
    }
    float rstd = rsqrtf(red[0] * (1.0f / DM) + LN_EPS);
    float2 gg = ((const float2*)g)[tid];
    float2 bb = ((const float2*)b)[tid];
    float h0 = dx * rstd * gg.x + bb.x;
    float h1 = dy * rstd * gg.y + bb.y;
    *(__half2*)(g_xn + afh_idx(row, 2 * tid, 48)) = __floats2half2_rn(h0, h1);
}

// ======================= depthwise conv (k=4) + SiLU, channel pairs =========
__global__ void conv_silu_kernel(const float* __restrict__ b_conv,
                                 const float* __restrict__ W_conv) {
    int idx = blockIdx.x * blockDim.x + threadIdx.x;
    if (idx >= (NROWS / 4) * (EE / 2)) return;
    int ep = idx % (EE / 2);
    int e0 = ep * 2;
    int r0 = (idx / (EE / 2)) * 4;
    int l0 = r0 % Lseq;
    const __half2* xin2 = (const __half2*)g_xin;

    float2 xa[7];
    #pragma unroll
    for (int j = 0; j < 3; j++) {
        if (l0 >= 3 - j) xa[j] = __half22float2(xin2[(size_t)(r0 - 3 + j) * (EE/2) + ep]);
        else             xa[j] = make_float2(0.f, 0.f);
    }
    #pragma unroll
    for (int j = 3; j < 7; j++)
        xa[j] = __half22float2(xin2[(size_t)(r0 - 3 + j) * (EE/2) + ep]);

    float4 wA = *(const float4*)(W_conv + e0 * 4);
    float4 wB = *(const float4*)(W_conv + e0 * 4 + 4);
    float bc0 = b_conv[e0], bc1 = b_conv[e0 + 1];

    #pragma unroll
    for (int i = 0; i < 4; i++) {
        float sx = bc0 + xa[i].x * wA.x + xa[i+1].x * wA.y + xa[i+2].x * wA.z + xa[i+3].x * wA.w;
        float sy = bc1 + xa[i].y * wB.x + xa[i+1].y * wB.y + xa[i+2].y * wB.z + xa[i+3].y * wB.w;
        float ax = sx / (1.0f + expf(-sx));
        float ay = sy / (1.0f + expf(-sy));
        *(__half2*)(g_cat + afh_idx(r0 + i, e0, KC_CAT)) = __floats2half2_rn(ax, ay);
    }
}

// ======================= fused prescan + scan + us ==========================
__global__ __launch_bounds__(256) void scan_kernel() {
    int chan = blockIdx.x;
    int bb = chan / DS, s = chan % DS;
    int t = threadIdx.x;
    __shared__ float sA[256], sB[256];
    float A = 1.0f, Bl = 0.0f;
    int base = bb * Lseq;
    #pragma unroll 4
    for (int i = 0; i < 16; i++) {
        size_t rofs = (size_t)(base + t * 16 + i);
        float ds    = g_xd[rofs * 32 + s];
        float dtraw = g_xd[rofs * 32 + 16 + s];
        float dt = fmaxf(dtraw, 0.0f) + log1pf(expf(-fabsf(dtraw)));
        float bt = ds * expf(-0.5f * dt);
        g_dt[rofs * DS + s] = dt;
        g_bt[rofs * DS + s] = bt;
        float a = expf(-dt);
        Bl = a * Bl + bt;
        A = a * A;
    }
    sA[t] = A; sB[t] = Bl;
    __syncthreads();
    for (int offp = 1; offp < 256; offp <<= 1) {
        float pA = 0.f, pB = 0.f;
        bool has = (t >= offp);
        if (has) { pA = sA[t - offp]; pB = sB[t - offp]; }
        __syncthreads();
        if (has) { sB[t] = sA[t] * pB + sB[t]; sA[t] = sA[t] * pA; }
        __syncthreads();
    }
    float v = (t == 0) ? 0.0f : sB[t - 1];
    for (int i = 0; i < 16; i++) {
        int l = t * 16 + i;
        int row = base + l;
        size_t off = (size_t)row * DS + s;
        float dt = g_dt[off];
        float bt = g_bt[off];
        v = expf(-dt) * v + bt;
        // us inline
        float kf = (float)(Lseq - 1 - l);
        float denom = expm1f(-dt);
        if (denom > -1e-30f) denom = -1e-30f;
        float us = expf(-kf * dt) * v + bt * expm1f(-kf * dt) / denom;
        g_cat[afh_idx(row, EE + s,      KC_CAT)] = __float2half_rn(us);
        g_cat[afh_idx(row, EE + DS + s, KC_CAT)] = __half(0.0f);
    }
}

// ======================= launch =============================================
extern "C" void kernel_launch(void* const* d_in, const int* in_sizes, int n_in,
                              void* d_out, int out_size) {
    const float* x      = (const float*)d_in[0];
    const float* ln_g   = (const float*)d_in[1];
    const float* ln_b   = (const float*)d_in[2];
    const float* W_in   = (const float*)d_in[3];
    const float* b_in   = (const float*)d_in[4];
    const float* W_conv = (const float*)d_in[5];
    const float* b_conv = (const float*)d_in[6];
    const float* W_xp   = (const float*)d_in[7];
    const float* b_xp   = (const float*)d_in[8];
    const float* W_dt   = (const float*)d_in[9];
    const float* b_dt   = (const float*)d_in[10];
    const float* W_us   = (const float*)d_in[11];
    const float* b_us   = (const float*)d_in[12];
    const float* W_out  = (const float*)d_in[13];
    const float* b_out  = (const float*)d_in[14];
    float* out = (float*)d_out;

    __half *xn, *xin, *cat, *winF, *wpsF, *xplF, *wolF, *comboF;
    float *xd, *bias32, *cbias;
    cudaGetSymbolAddress((void**)&xn,     g_xn);
    cudaGetSymbolAddress((void**)&xin,    g_xin);
    cudaGetSymbolAddress((void**)&cat,    g_cat);
    cudaGetSymbolAddress((void**)&xd,     g_xd);
    cudaGetSymbolAddress((void**)&bias32, g_bias32);
    cudaGetSymbolAddress((void**)&cbias,  g_cbias);
    cudaGetSymbolAddress((void**)&winF,   g_winF);
    cudaGetSymbolAddress((void**)&wpsF,   g_wpsF);
    cudaGetSymbolAddress((void**)&xplF,   g_xplF);
    cudaGetSymbolAddress((void**)&wolF,   g_wolF);
    cudaGetSymbolAddress((void**)&comboF, g_comboF);

    const int GEMM_SMEM = STAGES * STAGE_BYTES;  // 65536
    cudaFuncSetAttribute(gemm_f16_kernel<0>, cudaFuncAttributeMaxDynamicSharedMemorySize, GEMM_SMEM);
    cudaFuncSetAttribute(gemm_f16_kernel<1>, cudaFuncAttributeMaxDynamicSharedMemorySize, GEMM_SMEM);
    cudaFuncSetAttribute(gemm_f16_kernel<2>, cudaFuncAttributeMaxDynamicSharedMemorySize, GEMM_SMEM);

    // 1. merged weight prep (formats + wus2 + cbias + bias32)
    prep_kernel<<<NB_CB, 256>>>(W_in, W_out, W_xp, W_dt, W_us,
                                b_xp, b_dt, b_us, b_out);

    // 2. W_combo rows [0,1536): xplF @ wolF^T + W_out_hi -> comboF (MODE 2)
    gemm_f16_kernel<2><<<dim3(DM/128, EE/128), 256, GEMM_SMEM>>>(
        xplF, 48, wolF, nullptr, comboF, 0, DM, DM, W_out);

    // 3. LayerNorm -> A_f
    ln_kernel<<<NROWS, 384>>>(x, ln_g, ln_b);

    // 4. in-proj: (8192x768)@(768x1536) -> xin fp16 row-major
    gemm_f16_kernel<1><<<dim3(EE/128, NROWS/128), 256, GEMM_SMEM>>>(
        xn, 48, winF, b_in, xin, EE, EE, DM, nullptr);

    // 5. conv + silu -> g_cat A_f (k-blocks 0..95)
    conv_silu_kernel<<<((NROWS/4) * (EE/2) + 255) / 256, 256>>>(b_conv, W_conv);

    // 6. small proj: (8192x1536)@(1536x32) -> xd (ds|dt_raw)
    gemm_f16_kernel<0><<<dim3(1, NROWS/128), 256, GEMM_SMEM>>>(
        cat, KC_CAT, wpsF, bias32, xd, 32, 32, EE, nullptr);

    // 7. fused prescan + scan + us -> g_cat k-blocks 96/97
    scan_kernel<<<Bsz * DS, 256>>>();

    // 8. final: (8192x1568)@(1568x768) + cbias -> out
    gemm_f16_kernel<0><<<dim3(DM/128, NROWS/128), 256, GEMM_SMEM>>>(
        cat, KC_CAT, comboF, cbias, out, DM, DM, KCAT, nullptr);
}

// round 10
// speedup vs baseline: 1.2030x; 1.0084x over previous
#include <cuda_runtime.h>
#include <cuda_fp16.h>
#include <cstdint>
#include <math.h>

#define Bsz 2
#define Lseq 4096
#define DM 768
#define DS 16
#define EE 1536
#define NROWS (Bsz*Lseq)      // 8192
#define KCAT 1600             // 1536 (xact) + 16 (us) + 48 (zero pad), mult of 64
#define KC_CAT 100            // KCAT/16
#define LN_EPS 1e-5f

#define STAGE_BYTES 32768     // A tile 16KB + B tile 16KB (K-chunk 64, fp16)
#define GEMM_SMEM (3 * STAGE_BYTES)

// prep kernel block-region boundaries
#define NB_WIN  4608          // EE*DM/256
#define NB_WOL  (NB_WIN + 2304)
#define NB_XPL  (NB_WOL + 4608)
#define NB_WPS  (NB_XPL + 768)
#define NB_WUS2 (NB_WPS + 24)
#define NB_CB   (NB_WUS2 + 3)

// ======================= small PTX helpers ==================================
__device__ __forceinline__ uint32_t smem_u32(const void* p) {
    uint32_t a;
    asm("{ .reg .u64 t; cvta.to.shared.u64 t, %1; cvt.u32.u64 %0, t; }"
        : "=r"(a) : "l"(p));
    return a;
}
__device__ __forceinline__ void cp_async16(uint32_t dst, const void* src) {
    asm volatile("cp.async.cg.shared.global [%0], [%1], 16;"
                 :: "r"(dst), "l"(src) : "memory");
}
__device__ __forceinline__ void cp_commit() {
    asm volatile("cp.async.commit_group;" ::: "memory");
}
template<int N> __device__ __forceinline__ void cp_wait() {
    asm volatile("cp.async.wait_group %0;" :: "n"(N) : "memory");
}
__device__ __forceinline__ void mma_f16(float* c, const uint32_t* a, const uint32_t* b) {
    asm volatile("mma.sync.aligned.m16n8k16.row.col.f32.f16.f16.f32 "
        "{%0,%1,%2,%3}, {%4,%5,%6,%7}, {%8,%9}, {%0,%1,%2,%3};"
        : "+f"(c[0]), "+f"(c[1]), "+f"(c[2]), "+f"(c[3])
        : "r"(a[0]), "r"(a[1]), "r"(a[2]), "r"(a[3]), "r"(b[0]), "r"(b[1]));
}

// ---- fp16 fragment-native layouts (half-element index) ----------------------
__device__ __forceinline__ size_t afh_idx(int r, int k, int KC16) {
    size_t blk = (size_t)((r >> 4) * KC16 + (k >> 4));
    int b32 = (r & 7) * 16 + ((k >> 1) & 3) * 4 + ((r >> 3) & 1) + 2 * ((k >> 3) & 1);
    return blk * 256 + b32 * 2 + (k & 1);
}
__device__ __forceinline__ size_t bfh_idx(int n, int k, int KC16) {
    size_t blk = (size_t)((n >> 3) * KC16 + (k >> 4));
    int b32 = (n & 7) * 8 + ((k >> 1) & 3) * 2 + ((k >> 3) & 1);
    return blk * 128 + b32 * 2 + (k & 1);
}
__device__ __forceinline__ void bfh_inv(int idx, int KC16, int& n, int& k) {
    int blk = idx >> 7;
    int b32 = (idx & 127) >> 1, h = idx & 1;
    n = (blk / KC16) * 8 + (b32 >> 3);
    k = ((blk % KC16) << 4) | ((b32 & 1) << 3) | (((b32 >> 1) & 3) << 1) | h;
}
__device__ __forceinline__ void afh_inv(int idx, int KC16, int& r, int& k) {
    int blk = idx >> 8;
    int b32 = (idx & 255) >> 1, h = idx & 1;
    r = (blk / KC16) * 16 + ((b32 & 1) << 3) + (b32 >> 4);
    k = ((blk % KC16) << 4) | (((b32 >> 1) & 1) << 3) | (((b32 >> 2) & 3) << 1) | h;
}

// ======================= scratch ============================================
__device__ __align__(256) __half g_xn    [NROWS * DM];     // A_f (K=768)
__device__ __align__(256) __half g_xin   [NROWS * EE];     // fp16 row-major
__device__ __align__(256) __half g_cat   [NROWS * KCAT];   // A_f: xact|us|0
__device__ __align__(256) float  g_xd    [2 * NROWS * 32]; // ds|dt_raw, 2 K-split halves
__device__ float g_dt [NROWS * DS];
__device__ float g_bt [NROWS * DS];
__device__ float g_bias32[32];
__device__ float g_cbias [DM];
__device__ __align__(256) __half g_winF  [EE * DM];        // B_f: N=1536, K=768
__device__ __align__(256) __half g_wpsF  [128 * EE];       // B_f: N=128(pad), K=1536
__device__ __align__(256) __half g_xplF  [EE * DM];        // A_f: W_xp_low (M=1536,K=768)
__device__ __align__(256) __half g_wolF  [DM * DM];        // B_f: W_out_low (N=768,K=768)
__device__ __align__(256) __half g_comboF[(DM/8) * KC_CAT * 128]; // B_f: N=768, K=1600

// ======================= fp16 mma.sync GEMM (K-chunk 64) ====================
// MODE 0: float row-major out (+bias)   MODE 1: half row-major out (+bias)
// MODE 2: half out in bfh layout (k=row, n=col, KC16=KC_CAT), += addW row>=768
// grid.z>1: K split across z; bias added only by z==0; out += z*zstride bytes.
template<int MODE>
__global__ __launch_bounds__(256, 2) void gemm_f16_kernel(
    const __half* __restrict__ Af, int kc16s,
    const __half* __restrict__ Bf,
    const float* __restrict__ bias, void* __restrict__ Cv,
    int ldc, int Ndim, int K, const float* __restrict__ addW,
    size_t zstride)
{
    extern __shared__ __align__(16) char sm[];
    const int tid = threadIdx.x;
    const int wid = tid >> 5, lane = tid & 31;
    const int wm = wid >> 1, wn = wid & 1;
    const int g = lane >> 2, tg = lane & 3;
    const int KC16 = K >> 4;
    const int NCz = (K >> 6) / gridDim.z;
    const int c0 = blockIdx.z * NCz;
    const int mp0 = blockIdx.y * 8;
    const int ng0 = blockIdx.x * 16;
    const int m0 = blockIdx.y * 128, n0 = blockIdx.x * 128;
    const uint32_t smb = smem_u32(sm);

    auto load_chunk = [&](int i) {
        const int c = c0 + i;
        const uint32_t st = (uint32_t)(i % 3) * STAGE_BYTES;
        #pragma unroll
        for (int j = 0; j < 4; j++) {
            int L = tid + 256 * j;
            int pp = L >> 7, qq = (L >> 5) & 3, ll = L & 31;
            const __half* src = Af + ((size_t)(mp0 + pp) * kc16s + 4 * c + qq) * 256 + ll * 8;
            cp_async16(smb + st + (uint32_t)((pp * 4 + qq) * 512 + ll * 16), src);
        }
        #pragma unroll
        for (int j = 0; j < 4; j++) {
            int L = tid + 256 * j;
            int ng = L >> 6, qq = (L >> 4) & 3, ll = L & 15;
            const __half* src = Bf + ((size_t)(ng0 + ng) * KC16 + 4 * c + qq) * 128 + ll * 8;
            cp_async16(smb + st + 16384u + (uint32_t)((ng * 4 + qq) * 256 + ll * 16), src);
        }
        cp_commit();
    };

    float acc[2][8][4];
    #pragma unroll
    for (int mi = 0; mi < 2; mi++)
        #pragma unroll
        for (int ni = 0; ni < 8; ni++)
            #pragma unroll
            for (int q = 0; q < 4; q++) acc[mi][ni][q] = 0.0f;

    load_chunk(0); load_chunk(1);

    const char* stA_w = sm + wm * 4096 + g * 64 + tg * 16;
    const char* stB_w = sm + 16384 + wn * 8192 + g * 32 + tg * 8;

    for (int i = 0; i < NCz; i++) {
        cp_wait<1>();
        __syncthreads();
        if (i + 2 < NCz) load_chunk(i + 2); else cp_commit();

        const char* stA = stA_w + (i % 3) * STAGE_BYTES;
        const char* stB = stB_w + (i % 3) * STAGE_BYTES;

        #pragma unroll
        for (int kb = 0; kb < 4; kb++) {
            uint4 a0 = *(const uint4*)(stA + kb * 512);
            uint4 a1 = *(const uint4*)(stA + 2048 + kb * 512);
            uint2 bq[8];
            #pragma unroll
            for (int ni = 0; ni < 8; ni++)
                bq[ni] = *(const uint2*)(stB + ni * 1024 + kb * 256);
            #pragma unroll
            for (int ni = 0; ni < 8; ni++) {
                mma_f16(acc[0][ni], (const uint32_t*)&a0, (const uint32_t*)&bq[ni]);
                mma_f16(acc[1][ni], (const uint32_t*)&a1, (const uint32_t*)&bq[ni]);
            }
        }
    }

    if (MODE == 2) {
        __half* Cc = (__half*)Cv;
        #pragma unroll
        for (int mi = 0; mi < 2; mi++)
            #pragma unroll
            for (int ni = 0; ni < 8; ni++)
                #pragma unroll
                for (int q = 0; q < 4; q++) {
                    int row = m0 + wm * 32 + mi * 16 + g + ((q >> 1) << 3);
                    int col = n0 + wn * 64 + ni * 8 + tg * 2 + (q & 1);
                    float v = acc[mi][ni][q];
                    if (row >= DM) v += addW[(size_t)row * DM + col];
                    Cc[bfh_idx(col, row, KC_CAT)] = __float2half_rn(v);
                }
    } else {
        const bool ub = (blockIdx.z == 0);
        char* Cz = (char*)Cv + (size_t)blockIdx.z * zstride;
        #pragma unroll
        for (int mi = 0; mi < 2; mi++) {
            const int row = m0 + wm * 32 + mi * 16 + g;
            #pragma unroll
            for (int ni = 0; ni < 8; ni++) {
                const int col = n0 + wn * 64 + ni * 8 + tg * 2;
                if (col < Ndim) {
                    float bx = ub ? bias[col] : 0.0f;
                    float by = ub ? bias[col + 1] : 0.0f;
                    float v00 = acc[mi][ni][0] + bx, v01 = acc[mi][ni][1] + by;
                    float v10 = acc[mi][ni][2] + bx, v11 = acc[mi][ni][3] + by;
                    if (MODE == 1) {
                        __half* c0 = (__half*)Cz + (size_t)row * ldc;
                        __half* c1 = (__half*)Cz + (size_t)(row + 8) * ldc;
                        *(__half2*)(c0 + col) = __floats2half2_rn(v00, v01);
                        *(__half2*)(c1 + col) = __floats2half2_rn(v10, v11);
                    } else {
                        float* c0 = (float*)Cz + (size_t)row * ldc;
                        float* c1 = (float*)Cz + (size_t)(row + 8) * ldc;
                        *(float2*)(c0 + col) = make_float2(v00, v01);
                        *(float2*)(c1 + col) = make_float2(v10, v11);
                    }
                }
            }
        }
    }
}

// ======================= merged weight-prep kernel ==========================
__global__ void prep_kernel(const float* __restrict__ W_in,
                            const float* __restrict__ W_out,
                            const float* __restrict__ W_xp,
                            const float* __restrict__ W_dt,
                            const float* __restrict__ W_us,
                            const float* __restrict__ b_xp,
                            const float* __restrict__ b_dt,
                            const float* __restrict__ b_us,
                            const float* __restrict__ b_out) {
    __shared__ float red[8][16][32];
    const int blk = blockIdx.x;
    const int tid = threadIdx.x;

    if (blk < NB_WIN) {
        int idx = blk * 256 + tid;
        int n, k; bfh_inv(idx, 48, n, k);
        g_winF[idx] = __float2half_rn(W_in[(size_t)k * EE + n]);
    } else if (blk < NB_WOL) {
        int idx = (blk - NB_WIN) * 256 + tid;
        int n, k; bfh_inv(idx, 48, n, k);
        g_wolF[idx] = __float2half_rn(W_out[(size_t)k * DM + n]);
    } else if (blk < NB_XPL) {
        int idx = (blk - NB_WOL) * 256 + tid;
        int r, k; afh_inv(idx, 48, r, k);
        g_xplF[idx] = __float2half_rn(W_xp[(size_t)r * (DM + DS) + k]);
    } else if (blk < NB_WPS) {
        int idx = (blk - NB_XPL) * 256 + tid;
        int n, k; bfh_inv(idx, 96, n, k);
        float v = (n < DS)     ? W_xp[(size_t)k * (DM + DS) + DM + n]
                : (n < 2 * DS) ? W_dt[(size_t)k * DS + (n - DS)]
                : 0.0f;
        g_wpsF[idx] = __float2half_rn(v);
        if (blk == NB_XPL && tid < 32)
            g_bias32[tid] = (tid < DS) ? b_xp[DM + tid] : b_dt[tid - DS];
    } else if (blk < NB_WUS2) {
        // W_us2 = W_us(16x768) @ W_out_low(768x768): 24 blocks x 32 n each
        int bb = blk - NB_WPS;
        int n = bb * 32 + (tid & 31);
        int chunk = tid >> 5;
        float acc[16];
        #pragma unroll
        for (int s = 0; s < 16; s++) acc[s] = 0.0f;
        for (int j = chunk * 96; j < chunk * 96 + 96; j++) {
            float wo = W_out[(size_t)j * DM + n];
            #pragma unroll
            for (int s = 0; s < 16; s++)
                acc[s] = fmaf(W_us[(size_t)s * DM + j], wo, acc[s]);
        }
        #pragma unroll
        for (int s = 0; s < 16; s++) red[chunk][s][tid & 31] = acc[s];
        __syncthreads();
        for (int o = tid; o < 512; o += 256) {
            int s = o >> 5, ln = o & 31;
            float t = 0.0f;
            #pragma unroll
            for (int c = 0; c < 8; c++) t += red[c][s][ln];
            int nn = bb * 32 + ln;
            g_comboF[bfh_idx(nn, EE + s,          KC_CAT)] = __float2half_rn(t);
            g_comboF[bfh_idx(nn, EE + DS + s,     KC_CAT)] = __half(0.0f);
            g_comboF[bfh_idx(nn, EE + 2 * DS + s, KC_CAT)] = __half(0.0f);
            g_comboF[bfh_idx(nn, EE + 3 * DS + s, KC_CAT)] = __half(0.0f);
        }
    } else {
        int n = (blk - NB_WUS2) * 256 + tid;
        float acc = b_out[n];
        for (int j = 0; j < DM; j++)
            acc = fmaf(b_xp[j] + b_us[j], W_out[(size_t)j * DM + n], acc);
        g_cbias[n] = acc;
    }
}

// ======================= LayerNorm -> A_f fp16 (K=768), 384 thr =============
__global__ __launch_bounds__(384) void ln_kernel(const float* __restrict__ x,
                                                 const float* __restrict__ g,
                                                 const float* __restrict__ b) {
    int row = blockIdx.x, tid = threadIdx.x;
    const float2* xr = (const float2*)(x + (size_t)row * DM);
    float2 v = xr[tid];
    __shared__ float red[512];
    if (tid < 128) red[384 + tid] = 0.0f;
    red[tid] = v.x + v.y;
    __syncthreads();
    for (int off = 256; off > 0; off >>= 1) {
        if (tid < off) red[tid] += red[tid + off];
        __syncthreads();
    }
    float mu = red[0] * (1.0f / DM);
    __syncthreads();
    float dx = v.x - mu, dy = v.y - mu;
    red[tid] = dx * dx + dy * dy;
    __syncthreads();
    for (int off = 256; off > 0; off >>= 1) {
        if (tid < off) red[tid] += red[tid + off];
        __syncthreads();
    }
    float rstd = rsqrtf(red[0] * (1.0f / DM) + LN_EPS);
    float2 gg = ((const float2*)g)[tid];
    float2 bb = ((const float2*)b)[tid];
    float h0 = dx * rstd * gg.x + bb.x;
    float h1 = dy * rstd * gg.y + bb.y;
    *(__half2*)(g_xn + afh_idx(row, 2 * tid, 48)) = __floats2half2_rn(h0, h1);
}

// ======================= depthwise conv (k=4) + SiLU, channel pairs =========
__global__ void conv_silu_kernel(const float* __restrict__ b_conv,
                                 const float* __restrict__ W_conv) {
    int idx = blockIdx.x * blockDim.x + threadIdx.x;
    if (idx >= (NROWS / 4) * (EE / 2)) return;
    int ep = idx % (EE / 2);
    int e0 = ep * 2;
    int r0 = (idx / (EE / 2)) * 4;
    int l0 = r0 % Lseq;
    const __half2* xin2 = (const __half2*)g_xin;

    float2 xa[7];
    #pragma unroll
    for (int j = 0; j < 3; j++) {
        if (l0 >= 3 - j) xa[j] = __half22float2(xin2[(size_t)(r0 - 3 + j) * (EE/2) + ep]);
        else             xa[j] = make_float2(0.f, 0.f);
    }
    #pragma unroll
    for (int j = 3; j < 7; j++)
        xa[j] = __half22float2(xin2[(size_t)(r0 - 3 + j) * (EE/2) + ep]);

    float4 wA = *(const float4*)(W_conv + e0 * 4);
    float4 wB = *(const float4*)(W_conv + e0 * 4 + 4);
    float bc0 = b_conv[e0], bc1 = b_conv[e0 + 1];

    #pragma unroll
    for (int i = 0; i < 4; i++) {
        float sx = bc0 + xa[i].x * wA.x + xa[i+1].x * wA.y + xa[i+2].x * wA.z + xa[i+3].x * wA.w;
        float sy = bc1 + xa[i].y * wB.x + xa[i+1].y * wB.y + xa[i+2].y * wB.z + xa[i+3].y * wB.w;
        float ax = sx / (1.0f + expf(-sx));
        float ay = sy / (1.0f + expf(-sy));
        *(__half2*)(g_cat + afh_idx(r0 + i, e0, KC_CAT)) = __floats2half2_rn(ax, ay);
    }
}

// ======================= fused prescan + scan + us ==========================
__global__ __launch_bounds__(256) void scan_kernel() {
    int chan = blockIdx.x;
    int bb = chan / DS, s = chan % DS;
    int t = threadIdx.x;
    __shared__ float sA[256], sB[256];
    float A = 1.0f, Bl = 0.0f;
    int base = bb * Lseq;
    #pragma unroll 4
    for (int i = 0; i < 16; i++) {
        size_t rofs = (size_t)(base + t * 16 + i);
        float ds    = g_xd[rofs * 32 + s]      + g_xd[NROWS * 32 + rofs * 32 + s];
        float dtraw = g_xd[rofs * 32 + 16 + s] + g_xd[NROWS * 32 + rofs * 32 + 16 + s];
        float dt = fmaxf(dtraw, 0.0f) + log1pf(expf(-fabsf(dtraw)));
        float bt = ds * expf(-0.5f * dt);
        g_dt[rofs * DS + s] = dt;
        g_bt[rofs * DS + s] = bt;
        float a = expf(-dt);
        Bl = a * Bl + bt;
        A = a * A;
    }
    sA[t] = A; sB[t] = Bl;
    __syncthreads();
    for (int offp = 1; offp < 256; offp <<= 1) {
        float pA = 0.f, pB = 0.f;
        bool has = (t >= offp);
        if (has) { pA = sA[t - offp]; pB = sB[t - offp]; }
        __syncthreads();
        if (has) { sB[t] = sA[t] * pB + sB[t]; sA[t] = sA[t] * pA; }
        __syncthreads();
    }
    float v = (t == 0) ? 0.0f : sB[t - 1];
    for (int i = 0; i < 16; i++) {
        int l = t * 16 + i;
        int row = base + l;
        size_t off = (size_t)row * DS + s;
        float dt = g_dt[off];
        float bt = g_bt[off];
        v = expf(-dt) * v + bt;
        float kf = (float)(Lseq - 1 - l);
        float denom = expm1f(-dt);
        if (denom > -1e-30f) denom = -1e-30f;
        float us = expf(-kf * dt) * v + bt * expm1f(-kf * dt) / denom;
        g_cat[afh_idx(row, EE + s,          KC_CAT)] = __float2half_rn(us);
        g_cat[afh_idx(row, EE + DS + s,     KC_CAT)] = __half(0.0f);
        g_cat[afh_idx(row, EE + 2 * DS + s, KC_CAT)] = __half(0.0f);
        g_cat[afh_idx(row, EE + 3 * DS + s, KC_CAT)] = __half(0.0f);
    }
}

// ======================= launch =============================================
extern "C" void kernel_launch(void* const* d_in, const int* in_sizes, int n_in,
                              void* d_out, int out_size) {
    const float* x      = (const float*)d_in[0];
    const float* ln_g   = (const float*)d_in[1];
    const float* ln_b   = (const float*)d_in[2];
    const float* W_in   = (const float*)d_in[3];
    const float* b_in   = (const float*)d_in[4];
    const float* W_conv = (const float*)d_in[5];
    const float* b_conv = (const float*)d_in[6];
    const float* W_xp   = (const float*)d_in[7];
    const float* b_xp   = (const float*)d_in[8];
    const float* W_dt   = (const float*)d_in[9];
    const float* b_dt   = (const float*)d_in[10];
    const float* W_us   = (const float*)d_in[11];
    const float* b_us   = (const float*)d_in[12];
    const float* W_out  = (const float*)d_in[13];
    const float* b_out  = (const float*)d_in[14];
    float* out = (float*)d_out;

    __half *xn, *xin, *cat, *winF, *wpsF, *xplF, *wolF, *comboF;
    float *xd, *bias32, *cbias;
    cudaGetSymbolAddress((void**)&xn,     g_xn);
    cudaGetSymbolAddress((void**)&xin,    g_xin);
    cudaGetSymbolAddress((void**)&cat,    g_cat);
    cudaGetSymbolAddress((void**)&xd,     g_xd);
    cudaGetSymbolAddress((void**)&bias32, g_bias32);
    cudaGetSymbolAddress((void**)&cbias,  g_cbias);
    cudaGetSymbolAddress((void**)&winF,   g_winF);
    cudaGetSymbolAddress((void**)&wpsF,   g_wpsF);
    cudaGetSymbolAddress((void**)&xplF,   g_xplF);
    cudaGetSymbolAddress((void**)&wolF,   g_wolF);
    cudaGetSymbolAddress((void**)&comboF, g_comboF);

    cudaFuncSetAttribute(gemm_f16_kernel<0>, cudaFuncAttributeMaxDynamicSharedMemorySize, GEMM_SMEM);
    cudaFuncSetAttribute(gemm_f16_kernel<1>, cudaFuncAttributeMaxDynamicSharedMemorySize, GEMM_SMEM);
    cudaFuncSetAttribute(gemm_f16_kernel<2>, cudaFuncAttributeMaxDynamicSharedMemorySize, GEMM_SMEM);

    // 1. merged weight prep
    prep_kernel<<<NB_CB, 256>>>(W_in, W_out, W_xp, W_dt, W_us,
                                b_xp, b_dt, b_us, b_out);

    // 2. W_combo rows [0,1536): xplF @ wolF^T + W_out_hi -> comboF (MODE 2)
    gemm_f16_kernel<2><<<dim3(DM/128, EE/128, 1), 256, GEMM_SMEM>>>(
        xplF, 48, wolF, nullptr, comboF, 0, DM, DM, W_out, 0);

    // 3. LayerNorm -> A_f
    ln_kernel<<<NROWS, 384>>>(x, ln_g, ln_b);

    // 4. in-proj: (8192x768)@(768x1536) -> xin fp16 row-major
    gemm_f16_kernel<1><<<dim3(EE/128, NROWS/128, 1), 256, GEMM_SMEM>>>(
        xn, 48, winF, b_in, xin, EE, EE, DM, nullptr, 0);

    // 5. conv + silu -> g_cat A_f (k-blocks 0..95)
    conv_silu_kernel<<<((NROWS/4) * (EE/2) + 255) / 256, 256>>>(b_conv, W_conv);

    // 6. small proj: (8192x1536)@(1536x32) -> xd, K split over grid.z=2
    gemm_f16_kernel<0><<<dim3(1, NROWS/128, 2), 256, GEMM_SMEM>>>(
        cat, KC_CAT, wpsF, bias32, xd, 32, 32, EE, nullptr,
        (size_t)NROWS * 32 * sizeof(float));

    // 7. fused prescan + scan + us -> g_cat k-blocks 96..99
    scan_kernel<<<Bsz * DS, 256>>>();

    // 8. final: (8192x1600)@(1600x768) + cbias -> out
    gemm_f16_kernel<0><<<dim3(DM/128, NROWS/128, 1), 256, GEMM_SMEM>>>(
        cat, KC_CAT, comboF, cbias, out, DM, DM, KCAT, nullptr, 0);
}